// round 4
// baseline (speedup 1.0000x reference)
#include <cuda_runtime.h>
#include <math.h>

#define NB      262144
#define TT      80
#define NSTEP   30
#define RPB     128        // rows (threads) per block — small CTAs for phase interleave
#define TILE_STRIDE 33     // 32 staged elements (48..79) + 1 pad
#define OUT_STRIDE  31     // 30 outputs + 1 pad
#define DTC     0.1f
#define SMEM_BYTES ((2 * RPB * TILE_STRIDE + RPB * OUT_STRIDE) * sizeof(float))

__global__ __launch_bounds__(RPB)
void traj_kernel(const float* __restrict__ params,
                 const float* __restrict__ sv_v,
                 const float* __restrict__ hh,
                 const float* __restrict__ dvv,
                 const float* __restrict__ svY,
                 const float* __restrict__ lvY,
                 const float* __restrict__ lvv,
                 float* __restrict__ out)
{
    extern __shared__ float smem[];
    float* sY = smem;                          // [RPB][TILE_STRIDE]
    float* sV = smem + RPB * TILE_STRIDE;      // [RPB][TILE_STRIDE]
    float* sO = smem + 2 * RPB * TILE_STRIDE;  // [RPB][OUT_STRIDE]

    const int tid = threadIdx.x;
    const int r0  = blockIdx.x * RPB;

    // Cooperative, coalesced staging of lv_Y_seq1 / lv_v_seq1 elements 48..79.
    // byte offset = row*320 + 192 -> 16B aligned, 128B per row = 4 full sectors.
    #pragma unroll
    for (int k = 0; k < 8; ++k) {
        int idx = k * RPB + tid;
        int row = idx >> 3;      // 8 float4 quads per row
        int q   = idx & 7;
        size_t g = (size_t)(r0 + row) * TT + 48 + q * 4;
        float4 ya = *reinterpret_cast<const float4*>(lvY + g);
        float4 va = *reinterpret_cast<const float4*>(lvv + g);
        float* dy = sY + row * TILE_STRIDE + q * 4;
        float* dw = sV + row * TILE_STRIDE + q * 4;
        dy[0] = ya.x; dy[1] = ya.y; dy[2] = ya.z; dy[3] = ya.w;
        dw[0] = va.x; dw[1] = va.y; dw[2] = va.z; dw[3] = va.w;
    }

    // Per-row initial state at t=49 (one fetch per row per array; floor traffic).
    const size_t sbase = (size_t)(r0 + tid) * TT + 49;
    float v   = __ldg(sv_v + sbase);
    float gap = __ldg(hh   + sbase);
    float dvl = __ldg(dvv  + sbase);
    float y   = __ldg(svY  + sbase);

    // Params: broadcast loads, L1-resident.
    const float s0  = __ldg(params + 0);
    const float Thw = __ldg(params + 1);
    const float pa  = __ldg(params + 2);
    const float pb  = __ldg(params + 3);
    const float v0  = __ldg(params + 4);
    const float inv_c2 = 1.0f / (2.0f * sqrtf(pa * pb));
    const float inv_v0 = 1.0f / v0;

    __syncthreads();

    const float* myY = sY + tid * TILE_STRIDE + 2;  // element 50 = tile index 2
    const float* myV = sV + tid * TILE_STRIDE + 2;
    float* myO = sO + tid * OUT_STRIDE;

    #pragma unroll
    for (int i = 0; i < NSTEP; ++i) {
        // s_star = s0 + max(v*Thw + v*dv/(2*sqrt(a*b)), 0)  (NaN-propagating max)
        float t      = v * Thw + (v * dvl) * inv_c2;
        float relu   = !(t <= 0.0f) ? t : 0.0f;
        float s_star = s0 + relu;

        float rv  = v * inv_v0;
        float rv2 = rv * rv;
        float rs  = __fdividef(s_star, gap);
        float a_calc = pa * (1.0f - rv2 * rv2 - rs * rs);

        float v2  = v + a_calc * DTC;
        // where(v2 <= 0, -v/DT, a_calc); 1/0.1f rounds to exactly 10.0f
        float a_t = (v2 <= 0.0f) ? (-v * 10.0f) : a_calc;

        v   = v + a_t * DTC;
        dvl = v - myV[i];
        y   = y + v * DTC;
        gap = myY[i] - y;
        myO[i] = y;
    }

    __syncthreads();

    // Coalesced writeback: block writes RPB*NSTEP contiguous floats.
    const size_t obase = (size_t)r0 * NSTEP;
    #pragma unroll
    for (int k = 0; k < NSTEP; ++k) {
        int idx = k * RPB + tid;
        int row = idx / NSTEP;
        int col = idx - row * NSTEP;
        out[obase + idx] = sO[row * OUT_STRIDE + col];
    }
}

extern "C" void kernel_launch(void* const* d_in, const int* in_sizes, int n_in,
                              void* d_out, int out_size) {
    const float* params = (const float*)d_in[0];
    const float* sv_v1  = (const float*)d_in[1];
    const float* h1     = (const float*)d_in[2];
    const float* dv1    = (const float*)d_in[3];
    const float* sv_Y1  = (const float*)d_in[4];
    const float* lvY    = (const float*)d_in[5];
    const float* lvv    = (const float*)d_in[6];
    float* out = (float*)d_out;

    cudaFuncSetAttribute(traj_kernel,
                         cudaFuncAttributeMaxDynamicSharedMemorySize,
                         (int)SMEM_BYTES);
    traj_kernel<<<NB / RPB, RPB, SMEM_BYTES>>>(params, sv_v1, h1, dv1, sv_Y1,
                                               lvY, lvv, out);
}

// round 5
// speedup vs baseline: 1.0074x; 1.0074x over previous
#include <cuda_runtime.h>
#include <math.h>

#define NB      262144
#define TT      80
#define NSTEP   30
#define RPB     128        // rows (threads) per block
#define TILE_STRIDE 33     // 32 staged elements (48..79) + 1 pad
#define OUT_STRIDE  31     // 30 outputs + 1 pad
#define DTC     0.1f
#define SMEM_BYTES ((2 * RPB * TILE_STRIDE + RPB * OUT_STRIDE) * sizeof(float))

// (128, 4): reg budget = 65536/512 = 128 regs/thread — same budget that produced
// the fast 107-reg batched-LDG schedule at (256, 2). 4 CTAs/SM = 4 independent
// barrier domains for load/compute phase interleave.
__global__ __launch_bounds__(RPB, 4)
void traj_kernel(const float* __restrict__ params,
                 const float* __restrict__ sv_v,
                 const float* __restrict__ hh,
                 const float* __restrict__ dvv,
                 const float* __restrict__ svY,
                 const float* __restrict__ lvY,
                 const float* __restrict__ lvv,
                 float* __restrict__ out)
{
    extern __shared__ float smem[];
    float* sY = smem;                          // [RPB][TILE_STRIDE]
    float* sV = smem + RPB * TILE_STRIDE;      // [RPB][TILE_STRIDE]
    float* sO = smem + 2 * RPB * TILE_STRIDE;  // [RPB][OUT_STRIDE]

    const int tid = threadIdx.x;
    const int r0  = blockIdx.x * RPB;

    // Cooperative, coalesced staging of lv_Y_seq1 / lv_v_seq1 elements 48..79.
    // byte offset = row*320 + 192 -> 16B aligned, 128B per row = 4 full sectors.
    #pragma unroll
    for (int k = 0; k < 8; ++k) {
        int idx = k * RPB + tid;
        int row = idx >> 3;      // 8 float4 quads per row
        int q   = idx & 7;
        size_t g = (size_t)(r0 + row) * TT + 48 + q * 4;
        float4 ya = *reinterpret_cast<const float4*>(lvY + g);
        float4 va = *reinterpret_cast<const float4*>(lvv + g);
        float* dy = sY + row * TILE_STRIDE + q * 4;
        float* dw = sV + row * TILE_STRIDE + q * 4;
        dy[0] = ya.x; dy[1] = ya.y; dy[2] = ya.z; dy[3] = ya.w;
        dw[0] = va.x; dw[1] = va.y; dw[2] = va.z; dw[3] = va.w;
    }

    // Per-row initial state at t=49 (one fetch per row per array; floor traffic).
    const size_t sbase = (size_t)(r0 + tid) * TT + 49;
    float v   = __ldg(sv_v + sbase);
    float gap = __ldg(hh   + sbase);
    float dvl = __ldg(dvv  + sbase);
    float y   = __ldg(svY  + sbase);

    // Params: broadcast loads, L1-resident.
    const float s0  = __ldg(params + 0);
    const float Thw = __ldg(params + 1);
    const float pa  = __ldg(params + 2);
    const float pb  = __ldg(params + 3);
    const float v0  = __ldg(params + 4);
    const float inv_c2 = 1.0f / (2.0f * sqrtf(pa * pb));
    const float inv_v0 = 1.0f / v0;

    __syncthreads();

    const float* myY = sY + tid * TILE_STRIDE + 2;  // element 50 = tile index 2
    const float* myV = sV + tid * TILE_STRIDE + 2;
    float* myO = sO + tid * OUT_STRIDE;

    #pragma unroll
    for (int i = 0; i < NSTEP; ++i) {
        // s_star = s0 + max(v*Thw + v*dv/(2*sqrt(a*b)), 0)  (NaN-propagating max)
        float t      = v * Thw + (v * dvl) * inv_c2;
        float relu   = !(t <= 0.0f) ? t : 0.0f;
        float s_star = s0 + relu;

        float rv  = v * inv_v0;
        float rv2 = rv * rv;
        float rs  = __fdividef(s_star, gap);
        float a_calc = pa * (1.0f - rv2 * rv2 - rs * rs);

        float v2  = v + a_calc * DTC;
        // where(v2 <= 0, -v/DT, a_calc); 1/0.1f rounds to exactly 10.0f
        float a_t = (v2 <= 0.0f) ? (-v * 10.0f) : a_calc;

        v   = v + a_t * DTC;
        dvl = v - myV[i];
        y   = y + v * DTC;
        gap = myY[i] - y;
        myO[i] = y;
    }

    __syncthreads();

    // Coalesced writeback: block writes RPB*NSTEP contiguous floats.
    const size_t obase = (size_t)r0 * NSTEP;
    #pragma unroll
    for (int k = 0; k < NSTEP; ++k) {
        int idx = k * RPB + tid;
        int row = idx / NSTEP;
        int col = idx - row * NSTEP;
        out[obase + idx] = sO[row * OUT_STRIDE + col];
    }
}

extern "C" void kernel_launch(void* const* d_in, const int* in_sizes, int n_in,
                              void* d_out, int out_size) {
    const float* params = (const float*)d_in[0];
    const float* sv_v1  = (const float*)d_in[1];
    const float* h1     = (const float*)d_in[2];
    const float* dv1    = (const float*)d_in[3];
    const float* sv_Y1  = (const float*)d_in[4];
    const float* lvY    = (const float*)d_in[5];
    const float* lvv    = (const float*)d_in[6];
    float* out = (float*)d_out;

    cudaFuncSetAttribute(traj_kernel,
                         cudaFuncAttributeMaxDynamicSharedMemorySize,
                         (int)SMEM_BYTES);
    traj_kernel<<<NB / RPB, RPB, SMEM_BYTES>>>(params, sv_v1, h1, dv1, sv_Y1,
                                               lvY, lvv, out);
}

// round 6
// speedup vs baseline: 1.3779x; 1.3679x over previous
#include <cuda_runtime.h>
#include <math.h>

#define NB      262144
#define TT      80
#define NSTEP   30
#define RPB     256        // rows (threads) per block
#define TILE_STRIDE 33     // 32 staged elements (48..79) + 1 pad
#define OUT_STRIDE  31     // 30 outputs + 1 pad
#define DTC     0.1f
#define SMEM_BYTES ((2 * RPB * TILE_STRIDE + RPB * OUT_STRIDE) * sizeof(float))

__global__ __launch_bounds__(RPB, 2)
void traj_kernel(const float* __restrict__ params,
                 const float* __restrict__ sv_v,
                 const float* __restrict__ hh,
                 const float* __restrict__ dvv,
                 const float* __restrict__ svY,
                 const float* __restrict__ lvY,
                 const float* __restrict__ lvv,
                 float* __restrict__ out)
{
    extern __shared__ float smem[];
    float* sY = smem;                          // [RPB][TILE_STRIDE]
    float* sV = smem + RPB * TILE_STRIDE;      // [RPB][TILE_STRIDE]
    float* sO = smem + 2 * RPB * TILE_STRIDE;  // [RPB][OUT_STRIDE]

    const int tid  = threadIdx.x;
    const int wid  = tid >> 5;                 // warp id in block
    const int lane = tid & 31;
    const int r0   = blockIdx.x * RPB;
    const int wrow0 = wid * 32;                // first row (in-block) owned by this warp

    // ---- Warp-private staging: warp w loads ONLY its own 32 rows. ----
    // Rows wrow0..wrow0+31, elements 48..79 (8 float4 quads per row).
    // 32 rows * 8 quads = 256 quads = 8 iterations * 32 lanes.
    #pragma unroll
    for (int k = 0; k < 8; ++k) {
        int idx = k * 32 + lane;
        int row = wrow0 + (idx >> 3);   // 8 quads per row
        int q   = idx & 7;
        size_t g = (size_t)(r0 + row) * TT + 48 + q * 4;
        float4 ya = *reinterpret_cast<const float4*>(lvY + g);
        float4 va = *reinterpret_cast<const float4*>(lvv + g);
        float* dy = sY + row * TILE_STRIDE + q * 4;
        float* dw = sV + row * TILE_STRIDE + q * 4;
        dy[0] = ya.x; dy[1] = ya.y; dy[2] = ya.z; dy[3] = ya.w;
        dw[0] = va.x; dw[1] = va.y; dw[2] = va.z; dw[3] = va.w;
    }

    // Per-row initial state at t=49 (one fetch per row per array; floor traffic).
    const size_t sbase = (size_t)(r0 + tid) * TT + 49;
    float v   = __ldg(sv_v + sbase);
    float gap = __ldg(hh   + sbase);
    float dvl = __ldg(dvv  + sbase);
    float y   = __ldg(svY  + sbase);

    // Params: broadcast loads, L1-resident.
    const float s0  = __ldg(params + 0);
    const float Thw = __ldg(params + 1);
    const float pa  = __ldg(params + 2);
    const float pb  = __ldg(params + 3);
    const float v0  = __ldg(params + 4);
    const float inv_c2 = 1.0f / (2.0f * sqrtf(pa * pb));
    const float inv_v0 = 1.0f / v0;

    // Only this warp's data is needed — no block barrier anywhere.
    __syncwarp();

    const float* myY = sY + tid * TILE_STRIDE + 2;  // element 50 = tile index 2
    const float* myV = sV + tid * TILE_STRIDE + 2;
    float* myO = sO + tid * OUT_STRIDE;

    #pragma unroll
    for (int i = 0; i < NSTEP; ++i) {
        // s_star = s0 + max(v*Thw + v*dv/(2*sqrt(a*b)), 0)  (NaN-propagating max)
        float t      = v * Thw + (v * dvl) * inv_c2;
        float relu   = !(t <= 0.0f) ? t : 0.0f;
        float s_star = s0 + relu;

        float rv  = v * inv_v0;
        float rv2 = rv * rv;
        float rs  = __fdividef(s_star, gap);
        float a_calc = pa * (1.0f - rv2 * rv2 - rs * rs);

        float v2  = v + a_calc * DTC;
        // where(v2 <= 0, -v/DT, a_calc); 1/0.1f rounds to exactly 10.0f
        float a_t = (v2 <= 0.0f) ? (-v * 10.0f) : a_calc;

        v   = v + a_t * DTC;
        dvl = v - myV[i];
        y   = y + v * DTC;
        gap = myY[i] - y;
        myO[i] = y;
    }

    __syncwarp();

    // ---- Warp-private coalesced writeback: this warp's 32 rows * 30 outputs
    // = 960 contiguous floats starting at (r0 + wrow0) * NSTEP (3840B-aligned).
    const size_t obase = (size_t)(r0 + wrow0) * NSTEP;
    const float* wO = sO + wrow0 * OUT_STRIDE;
    #pragma unroll
    for (int k = 0; k < NSTEP; ++k) {
        int idx = k * 32 + lane;
        int row = idx / NSTEP;
        int col = idx - row * NSTEP;
        out[obase + idx] = wO[row * OUT_STRIDE + col];
    }
}

extern "C" void kernel_launch(void* const* d_in, const int* in_sizes, int n_in,
                              void* d_out, int out_size) {
    const float* params = (const float*)d_in[0];
    const float* sv_v1  = (const float*)d_in[1];
    const float* h1     = (const float*)d_in[2];
    const float* dv1    = (const float*)d_in[3];
    const float* sv_Y1  = (const float*)d_in[4];
    const float* lvY    = (const float*)d_in[5];
    const float* lvv    = (const float*)d_in[6];
    float* out = (float*)d_out;

    cudaFuncSetAttribute(traj_kernel,
                         cudaFuncAttributeMaxDynamicSharedMemorySize,
                         (int)SMEM_BYTES);
    traj_kernel<<<NB / RPB, RPB, SMEM_BYTES>>>(params, sv_v1, h1, dv1, sv_Y1,
                                               lvY, lvv, out);
}

// round 7
// speedup vs baseline: 1.4399x; 1.0450x over previous
#include <cuda_runtime.h>
#include <math.h>
#include <stdint.h>

#define NB      262144
#define TT      80
#define NSTEP   30
#define RPB     256               // rows (threads) per block / per tile
#define NTILES  (NB / RPB)        // 1024
#define TS      34                // tile row stride in floats: 8B-aligned for cp.async, 2-way LDS conflict
#define DTC     0.1f
#define GRID    152               // persistent: 1 CTA per SM on GB300
#define BUFELEMS (2 * RPB * TS)   // sY + sV for one buffer
#define SMEM_BYTES (2 * BUFELEMS * sizeof(float))

__device__ __forceinline__ void cpa8(uint32_t dst, const float* src) {
    asm volatile("cp.async.ca.shared.global [%0], [%1], 8;" :: "r"(dst), "l"(src));
}

__global__ __launch_bounds__(RPB, 1)
void traj_kernel(const float* __restrict__ params,
                 const float* __restrict__ sv_v,
                 const float* __restrict__ hh,
                 const float* __restrict__ dvv,
                 const float* __restrict__ svY,
                 const float* __restrict__ lvY,
                 const float* __restrict__ lvv,
                 float* __restrict__ out)
{
    extern __shared__ float smem[];      // [2][2][RPB][TS]  (buf, {Y,V}, row, elem)
    const int tid   = threadIdx.x;
    const int wid   = tid >> 5;
    const int lane  = tid & 31;
    const int wrow0 = wid * 32;
    const uint32_t smem_u32 = (uint32_t)__cvta_generic_to_shared(smem);

    // Params: broadcast, L1-resident.
    const float s0  = __ldg(params + 0);
    const float Thw = __ldg(params + 1);
    const float pa  = __ldg(params + 2);
    const float pb  = __ldg(params + 3);
    const float v0  = __ldg(params + 4);
    const float inv_c2 = 1.0f / (2.0f * sqrtf(pa * pb));
    const float inv_v0 = 1.0f / v0;

    int t   = blockIdx.x;
    int buf = 0;
    float nv = 0.f, ngap = 0.f, ndvl = 0.f, ny = 0.f;

    // ---- Prologue: async-stage tile t into buffer 0, prefetch its scalars. ----
    {
        const int r0 = t * RPB;
        #pragma unroll
        for (int k = 0; k < 16; ++k) {
            int idx = k * 32 + lane;
            int row = wrow0 + (idx >> 4);   // 16 8B-chunks per row
            int c   = idx & 15;
            size_t g = (size_t)(r0 + row) * TT + 48 + c * 2;
            uint32_t dY = smem_u32 + (uint32_t)(row * TS + c * 2) * 4u;
            uint32_t dV = dY + (uint32_t)(RPB * TS) * 4u;
            cpa8(dY, lvY + g);
            cpa8(dV, lvv + g);
        }
        asm volatile("cp.async.commit_group;");
        size_t sb = (size_t)(r0 + tid) * TT + 49;
        nv   = __ldg(sv_v + sb);
        ngap = __ldg(hh   + sb);
        ndvl = __ldg(dvv  + sb);
        ny   = __ldg(svY  + sb);
    }

    while (t < NTILES) {
        const int tn = t + (int)gridDim.x;
        float v = nv, gap = ngap, dvl = ndvl, y = ny;

        if (tn < NTILES) {
            // ---- Issue next tile's loads into the other buffer (overlaps this compute). ----
            const int r0n = tn * RPB;
            const uint32_t ob = (uint32_t)((buf ^ 1) * BUFELEMS) * 4u;
            #pragma unroll
            for (int k = 0; k < 16; ++k) {
                int idx = k * 32 + lane;
                int row = wrow0 + (idx >> 4);
                int c   = idx & 15;
                size_t g = (size_t)(r0n + row) * TT + 48 + c * 2;
                uint32_t dY = smem_u32 + ob + (uint32_t)(row * TS + c * 2) * 4u;
                uint32_t dV = dY + (uint32_t)(RPB * TS) * 4u;
                cpa8(dY, lvY + g);
                cpa8(dV, lvv + g);
            }
            asm volatile("cp.async.commit_group;");
            size_t sb = (size_t)(r0n + tid) * TT + 49;
            nv   = __ldg(sv_v + sb);
            ngap = __ldg(hh   + sb);
            ndvl = __ldg(dvv  + sb);
            ny   = __ldg(svY  + sb);
            asm volatile("cp.async.wait_group 1;");  // current tile's group done; next stays in flight
        } else {
            asm volatile("cp.async.wait_group 0;");
        }
        __syncwarp();

        // ---- Compute this warp's 32 rows from buffer `buf`. ----
        float* bY  = smem + buf * BUFELEMS;
        float* myY = bY + tid * TS + 2;          // element 50 = tile index 2
        const float* myV = myY + RPB * TS;

        #pragma unroll
        for (int i = 0; i < NSTEP; ++i) {
            // s_star = s0 + max(v*Thw + v*dv/(2*sqrt(a*b)), 0)  (NaN-propagating max)
            float tt     = v * Thw + (v * dvl) * inv_c2;
            float relu   = !(tt <= 0.0f) ? tt : 0.0f;
            float s_star = s0 + relu;

            float rv  = v * inv_v0;
            float rv2 = rv * rv;
            float rs  = __fdividef(s_star, gap);
            float a_calc = pa * (1.0f - rv2 * rv2 - rs * rs);

            float v2  = v + a_calc * DTC;
            // where(v2 <= 0, -v/DT, a_calc); 1/0.1f rounds to exactly 10.0f
            float a_t = (v2 <= 0.0f) ? (-v * 10.0f) : a_calc;

            v   = v + a_t * DTC;
            dvl = v - myV[i];
            y   = y + v * DTC;
            gap = myY[i] - y;     // last read of lv_Y slot i ...
            myY[i] = y;           // ... reuse it to stage the output in place
        }
        __syncwarp();

        // ---- Warp-private coalesced writeback: 960 contiguous floats. ----
        const size_t obase = (size_t)(t * RPB + wrow0) * NSTEP;
        const float* wO = bY + wrow0 * TS;
        #pragma unroll
        for (int k = 0; k < NSTEP; ++k) {
            int idx = k * 32 + lane;
            int row = idx / NSTEP;
            int col = idx - row * NSTEP;
            out[obase + idx] = wO[row * TS + 2 + col];
        }
        __syncwarp();   // lanes' SMEM reads done before this buffer is refilled next iteration

        buf ^= 1;
        t = tn;
    }
}

extern "C" void kernel_launch(void* const* d_in, const int* in_sizes, int n_in,
                              void* d_out, int out_size) {
    const float* params = (const float*)d_in[0];
    const float* sv_v1  = (const float*)d_in[1];
    const float* h1     = (const float*)d_in[2];
    const float* dv1    = (const float*)d_in[3];
    const float* sv_Y1  = (const float*)d_in[4];
    const float* lvY    = (const float*)d_in[5];
    const float* lvv    = (const float*)d_in[6];
    float* out = (float*)d_out;

    cudaFuncSetAttribute(traj_kernel,
                         cudaFuncAttributeMaxDynamicSharedMemorySize,
                         (int)SMEM_BYTES);
    traj_kernel<<<GRID, RPB, SMEM_BYTES>>>(params, sv_v1, h1, dv1, sv_Y1,
                                           lvY, lvv, out);
}